// round 17
// baseline (speedup 1.0000x reference)
#include <cuda_runtime.h>
#include <math.h>

#define B_TOTAL 65536
#define OBS 64
#define ACTD 16
#define IND 145
#define HID 256
#define FEAT 128
#define NENV 64
#define EMB 32
#define ROWS 32
#define NTHREADS 512

typedef unsigned long long u64;

__device__ __forceinline__ u64 fma2(u64 a, u64 b, u64 c) {
    u64 d; asm("fma.rn.f32x2 %0,%1,%2,%3;" : "=l"(d) : "l"(a), "l"(b), "l"(c)); return d;
}
__device__ __forceinline__ u64 pack2(float x, float y) {
    u64 d; asm("mov.b64 %0,{%1,%2};" : "=l"(d) : "f"(x), "f"(y)); return d;
}
__device__ __forceinline__ void unpack2(u64 v, float& x, float& y) {
    asm("mov.b64 {%0,%1},%2;" : "=f"(x), "=f"(y) : "l"(v));
}

// ---- repacked weights (k-quads): Wq[j][c] = (W[4j..4j+3][c])
#define KQ0 37   // ceil(145/4), zero-padded
#define KQ1 64
#define KQ2 64
__device__ float4 g_w0q[KQ0 * 256];
__device__ float4 g_w1q[KQ1 * 256];
__device__ float4 g_w2q[KQ2 * 128];

__global__ void repack_kernel(const float* __restrict__ W0,
                              const float* __restrict__ W1,
                              const float* __restrict__ W2) {
    int i = blockIdx.x * 256 + threadIdx.x;
    if (i < KQ0 * 256) {
        int j = i >> 8, c = i & 255;
        float4 v;
        v.x = (4 * j + 0 < IND) ? W0[(4 * j + 0) * 256 + c] : 0.0f;
        v.y = (4 * j + 1 < IND) ? W0[(4 * j + 1) * 256 + c] : 0.0f;
        v.z = (4 * j + 2 < IND) ? W0[(4 * j + 2) * 256 + c] : 0.0f;
        v.w = (4 * j + 3 < IND) ? W0[(4 * j + 3) * 256 + c] : 0.0f;
        g_w0q[i] = v;
    } else if (i < KQ0 * 256 + KQ1 * 256) {
        int idx = i - KQ0 * 256;
        int j = idx >> 8, c = idx & 255;
        g_w1q[idx] = make_float4(W1[(4 * j + 0) * 256 + c], W1[(4 * j + 1) * 256 + c],
                                 W1[(4 * j + 2) * 256 + c], W1[(4 * j + 3) * 256 + c]);
    } else if (i < KQ0 * 256 + KQ1 * 256 + KQ2 * 128) {
        int idx = i - KQ0 * 256 - KQ1 * 256;
        int j = idx >> 7, c = idx & 127;
        g_w2q[idx] = make_float4(W2[(4 * j + 0) * 128 + c], W2[(4 * j + 1) * 128 + c],
                                 W2[(4 * j + 2) * 128 + c], W2[(4 * j + 3) * 128 + c]);
    }
}

// ---- shared memory layout (float offsets), all bases 16B-aligned ----
#define XS 148                 // X row stride
#define HS 264                 // H0/H1 row stride (so 2 tiles = 16896 = W tile exactly)
#define FS 132                 // feat row stride
#define OFF_X     0            // 32*148 = 4736 ; feat (32*132=4224) aliases
#define OFF_FEAT  0
#define OFF_H0    4736         // 32*264 = 8448 -> 13184
#define OFF_H1    13184        // -> 21632
#define OFF_WT    4736         // proj W tile 128c*33f4 = 16896 fl -> 21632 (aliases H0+H1, dead)
#define OFF_EEMB  21632        // 2048 -> 23680
#define OFF_BEST  23680        // 32*32 = 1024 -> 24704
#define OFF_COEF  24704        // 64 -> 24768
#define SMEM_FLOATS 24768      // 99072 bytes -> 2 CTAs/SM (198144 <= 228KB)

// Dense layer, row-major in/out, quad-k weights, packed f32x2 FMA.
// tx = tid&63 -> cols {tx+64jj}; ty = tid>>6 (0..7) -> rows [ty*4, ty*4+4)
template<int NJ, int KQ>
__device__ __forceinline__ void dense_q(
    const float* __restrict__ in_rm, int in_stride,
    const float4* __restrict__ Wq, const float* __restrict__ bias, int C,
    float* __restrict__ out_rm, int out_stride, int tid)
{
    const int tx = tid & 63;
    const int ty = tid >> 6;
    u64 acc[4][NJ];
#pragma unroll
    for (int jj = 0; jj < NJ; jj++) {
        float bb = __ldg(&bias[tx + 64 * jj]);
        u64 b2 = pack2(bb, 0.0f);
#pragma unroll
        for (int r = 0; r < 4; r++) acc[r][jj] = b2;
    }
    const float* xrow = in_rm + (ty * 4) * in_stride;
#pragma unroll 2
    for (int j = 0; j < KQ; j++) {
        ulonglong2 w[NJ];
#pragma unroll
        for (int jj = 0; jj < NJ; jj++)
            w[jj] = *(const ulonglong2*)&Wq[j * C + tx + 64 * jj];
#pragma unroll
        for (int r = 0; r < 4; r++) {
            ulonglong2 xq = *(const ulonglong2*)(xrow + r * in_stride + 4 * j);
#pragma unroll
            for (int jj = 0; jj < NJ; jj++) {
                acc[r][jj] = fma2(xq.x, w[jj].x, acc[r][jj]);
                acc[r][jj] = fma2(xq.y, w[jj].y, acc[r][jj]);
            }
        }
    }
#pragma unroll
    for (int r = 0; r < 4; r++) {
#pragma unroll
        for (int jj = 0; jj < NJ; jj++) {
            float lo, hi; unpack2(acc[r][jj], lo, hi);
            float s = lo + hi;
            out_rm[(ty * 4 + r) * out_stride + tx + 64 * jj] = fmaxf(s, 0.01f * s);
        }
    }
}

extern __shared__ float sm[];

__global__ void __launch_bounds__(NTHREADS, 2)
udp_encoder_kernel(
    const float* __restrict__ obs,  const float* __restrict__ act,
    const float* __restrict__ obs2, const float* __restrict__ rew,
    const float* __restrict__ b0,   const float* __restrict__ b1,
    const float* __restrict__ b2,   const float* __restrict__ Wp,
    const float* __restrict__ ee,   const float* __restrict__ sig,
    float* __restrict__ out)
{
    const int tid = threadIdx.x;
    const size_t row0 = (size_t)blockIdx.x * ROWS;

    // ---- stage e_emb + sigma coefficients ----
    for (int i = tid; i < NENV * EMB; i += NTHREADS) sm[OFF_EEMB + i] = ee[i];
    if (tid < NENV) {
        float s = sig[tid];
        sm[OFF_COEF + tid] = -1.0f / (64.0f * s * s);
    }

    // ---- build row-major input tile X[r][k], stride 148, k=145..147 zero ----
    for (int i = tid; i < ROWS * OBS; i += NTHREADS) {
        int r = i >> 6, k = i & 63;
        float o  = obs [(row0 + r) * OBS + k];
        float o2 = obs2[(row0 + r) * OBS + k];
        sm[OFF_X + r * XS + k]      = o;
        sm[OFF_X + r * XS + 64 + k] = o2 - o;
    }
    for (int i = tid; i < ROWS * ACTD; i += NTHREADS) {
        int r = i >> 4, k = i & 15;
        sm[OFF_X + r * XS + 128 + k] = act[(row0 + r) * ACTD + k];
    }
    if (tid < ROWS) {
        sm[OFF_X + tid * XS + 144] = rew[row0 + tid];
        sm[OFF_X + tid * XS + 145] = 0.0f;
        sm[OFF_X + tid * XS + 146] = 0.0f;
        sm[OFF_X + tid * XS + 147] = 0.0f;
    }
    __syncthreads();

    // ---- MLP ----
    dense_q<4, KQ0>(sm + OFF_X,  XS, g_w0q, b0, 256, sm + OFF_H0,   HS, tid);
    __syncthreads();
    dense_q<4, KQ1>(sm + OFF_H0, HS, g_w1q, b1, 256, sm + OFF_H1,   HS, tid);
    __syncthreads();
    dense_q<2, KQ2>(sm + OFF_H1, HS, g_w2q, b2, 128, sm + OFF_FEAT, FS, tid);
    // (sync at top of projection loop covers feat/H readers)

    // ==== projection: 16 warps, each owns 2 rows end-to-end ====
    const int lane = tid & 31;
    const int wrp  = tid >> 5;          // 16 warps x 2 rows = 32 rows
    const int nl   = lane >> 3;         // env within group (0..3)
    const int eb   = lane & 7;          // lane's emb dims: e = eb + 8j
    const int r0   = wrp * 2;

    float mind[2]; int midx[2];         // replicated across lanes of warp
#pragma unroll
    for (int i = 0; i < 2; i++) { mind[i] = 3.0e38f; midx[i] = 0; }

    float4* wt = (float4*)(sm + OFF_WT);          // [c][kq], stride 33 f4
    const float4* WpQ = (const float4*)Wp;        // [n][e][kq]
    const float* fbase = sm + OFF_FEAT + r0 * FS;

    for (int g = 0; g < 16; g++) {
        __syncthreads();   // previous tile's readers done (g=0: feat/H1 final)
        // stage W tile: warp covers c = wrp + 16*i, i<8; lane = kq (coalesced LDG, clean STS)
#pragma unroll
        for (int i = 0; i < 8; i++) {
            int c = wrp + 16 * i;
            int n_l = c >> 5, e = c & 31;
            float4 v = WpQ[((size_t)(g * 4 + n_l) * EMB + e) * 32 + lane];
            wt[c * 33 + lane] = v;
        }
        __syncthreads();

        const int n = g * 4 + nl;
        float eev[4];
#pragma unroll
        for (int j = 0; j < 4; j++) eev[j] = sm[OFF_EEMB + n * EMB + eb + 8 * j];
        float cf = sm[OFF_COEF + n];

        u64 acc[2][4];
#pragma unroll
        for (int r = 0; r < 2; r++)
#pragma unroll
            for (int j = 0; j < 4; j++) acc[r][j] = 0ULL;

#pragma unroll 2
        for (int kq = 0; kq < 32; kq++) {
            ulonglong2 w[4];
#pragma unroll
            for (int j = 0; j < 4; j++)
                w[j] = *(const ulonglong2*)&wt[(nl * 32 + eb + 8 * j) * 33 + kq];
#pragma unroll
            for (int r = 0; r < 2; r++) {
                ulonglong2 xq = *(const ulonglong2*)(fbase + r * FS + 4 * kq);
#pragma unroll
                for (int j = 0; j < 4; j++) {
                    acc[r][j] = fma2(xq.x, w[j].x, acc[r][j]);
                    acc[r][j] = fma2(xq.y, w[j].y, acc[r][j]);
                }
            }
        }

        // epilogue: distances, argmin, winner-copy — all in-warp
#pragma unroll
        for (int r = 0; r < 2; r++) {
            float f[4];
#pragma unroll
            for (int j = 0; j < 4; j++) {
                float lo, hi; unpack2(acc[r][j], lo, hi);
                f[j] = lo + hi;
            }
            float ss = 0.0f;
#pragma unroll
            for (int j = 0; j < 4; j++) {
                float d = f[j] - eev[j];
                ss = fmaf(d, d, ss);
            }
            ss += __shfl_xor_sync(0xffffffffu, ss, 1);
            ss += __shfl_xor_sync(0xffffffffu, ss, 2);
            ss += __shfl_xor_sync(0xffffffffu, ss, 4);
            float dv = expf(ss * cf);
            if (eb == 0)
                out[(size_t)B_TOTAL * 66 + (row0 + r0 + r) * 64 + n] = dv;

            float dred = (eb == 0) ? dv : 3.0e38f;
            int   nred = n;
#pragma unroll
            for (int s = 8; s <= 16; s <<= 1) {
                float d2 = __shfl_xor_sync(0xffffffffu, dred, s);
                int   n2 = __shfl_xor_sync(0xffffffffu, nred, s);
                if (d2 < dred || (d2 == dred && n2 < nred)) { dred = d2; nred = n2; }
            }
            float wd = __shfl_sync(0xffffffffu, dred, 0);
            int   wn2 = __shfl_sync(0xffffffffu, nred, 0);

            if (wd < mind[r]) {
                mind[r] = wd; midx[r] = wn2;
                if (nl == (wn2 & 3)) {
#pragma unroll
                    for (int j = 0; j < 4; j++)
                        sm[OFF_BEST + (r0 + r) * EMB + eb + 8 * j] = f[j];
                }
            }
        }
    }
    __syncwarp();   // BEST writes visible within warp

    // ==== final outputs (per-warp; rows are warp-private) ====
#pragma unroll
    for (int r = 0; r < 2; r++) {
        size_t grow = row0 + r0 + r;
        int m = midx[r];
        out[grow * EMB + lane] = sm[OFF_BEST + (r0 + r) * EMB + lane];                 // chosen_embedding
        out[(size_t)B_TOTAL * 34 + grow * EMB + lane] = sm[OFF_EEMB + m * EMB + lane]; // chosen_mean
        if (lane == 0) {
            out[(size_t)B_TOTAL * 32 + grow] = mind[r];    // chosen_dist
            out[(size_t)B_TOTAL * 33 + grow] = (float)m;   // idx
        }
    }
}

extern "C" void kernel_launch(void* const* d_in, const int* in_sizes, int n_in,
                              void* d_out, int out_size) {
    const float* obs  = (const float*)d_in[0];
    const float* act  = (const float*)d_in[1];
    const float* obs2 = (const float*)d_in[2];
    const float* rew  = (const float*)d_in[3];
    const float* W0   = (const float*)d_in[4];
    const float* b0   = (const float*)d_in[5];
    const float* W1   = (const float*)d_in[6];
    const float* b1   = (const float*)d_in[7];
    const float* W2   = (const float*)d_in[8];
    const float* b2   = (const float*)d_in[9];
    const float* Wp   = (const float*)d_in[10];
    const float* ee   = (const float*)d_in[11];
    const float* sig  = (const float*)d_in[12];
    float* out = (float*)d_out;

    int total = KQ0 * 256 + KQ1 * 256 + KQ2 * 128;
    repack_kernel<<<(total + 255) / 256, 256>>>(W0, W1, W2);

    const size_t smem_bytes = (size_t)SMEM_FLOATS * sizeof(float); // 99072
    cudaFuncSetAttribute(udp_encoder_kernel,
                         cudaFuncAttributeMaxDynamicSharedMemorySize, (int)smem_bytes);

    dim3 grid(B_TOTAL / ROWS);   // 2048 blocks
    dim3 block(NTHREADS);
    udp_encoder_kernel<<<grid, block, smem_bytes>>>(
        obs, act, obs2, rew, b0, b1, b2, Wp, ee, sig, out);
}